// round 17
// baseline (speedup 1.0000x reference)
#include <cuda_runtime.h>

#define NB    16384
#define SN    81
#define HID   32
#define OBSW  162
#define BPB   8
#define NTHREADS (BPB * 32)

// out layout: [0,NB) symbolic | [NB,2NB) imm | [2NB,3NB) next | [3NB,..) nsc BxSN
//
// Floor kernel (R16, 57.8 us) + ILP trims: nsc broadcast via shuffle (sh_nsc
// eliminated), h1 split into 3 accumulators, h2 into 2.

__global__ __launch_bounds__(NTHREADS) void gdvpn_kernel(
    const float* __restrict__ obs,   // B x 162
    const float* __restrict__ ac,    // B x 81 x 81
    const float* __restrict__ W1,    // 81 x 32
    const float* __restrict__ W2,    // 32 x 32
    const float* __restrict__ W3,    // 32
    const float* __restrict__ b3,    // 1
    float* __restrict__ out)
{
    // sh[w][5*j+off] = ac[b, j, j+D[off]] (0 if invalid), D = {-9,-1,0,+1,+9}.
    __shared__ float sh[BPB][SN * 5];

    const int w    = threadIdx.x >> 5;
    const int lane = threadIdx.x & 31;
    const int b    = blockIdx.x * BPB + w;
    const float* acb = ac + (size_t)b * (SN * SN);

    // ---- Phase 0: prefetch demand (overlaps under the gather) ----
    float dem[3];
    #pragma unroll
    for (int k = 0; k < 3; ++k) {
        const int t = lane + 32 * k;
        dem[k] = (t < SN) ? __ldcs(obs + (size_t)b * OBSW + SN + t) : 0.0f;
    }

    // ---- Phase 1: gather (13 independent predicated loads per lane) ----
    #pragma unroll
    for (int it = 0; it < 13; ++it) {
        const int q = lane + it * 32;
        if (q < SN * 5) {
            const int j   = q / 5;
            const int off = q - 5 * j;
            const int c   = j % 9;
            int d; bool valid;
            switch (off) {
                case 0: d = -9; valid = (j >= 9);     break;
                case 1: d = -1; valid = (c > 0);      break;
                case 2: d =  0; valid = true;         break;
                case 3: d =  1; valid = (c < 8);      break;
                default:d =  9; valid = (j < SN - 9); break;
            }
            sh[w][q] = valid ? __ldcs(acb + 82 * j + d) : 0.0f;
        }
    }
    __syncwarp();

    // ---- Phase 2: nsc + served; nsc stays in v[3] registers ----
    float v[3];
    float served = 0.0f;
    #pragma unroll
    for (int k = 0; k < 3; ++k) {
        const int t = lane + k * 32;
        float x = 0.0f;
        if (t < SN) {
            const int c = t % 9;
            x = sh[w][5 * t + 2];
            if (t >= 9)      x += sh[w][5 * (t - 9) + 4];
            if (t < SN - 9)  x += sh[w][5 * (t + 9) + 0];
            if (c > 0)       x += sh[w][5 * (t - 1) + 3];
            if (c < 8)       x += sh[w][5 * (t + 1) + 1];

            __stcs(out + (size_t)3 * NB + (size_t)b * SN + t, x);
            served += fminf(x, dem[k]);
        }
        v[k] = x;
    }

    #pragma unroll
    for (int o = 16; o > 0; o >>= 1)
        served += __shfl_down_sync(0xFFFFFFFFu, served, o);
    const float imm = __shfl_sync(0xFFFFFFFFu, served, 0);

    // ---- Phase 3: MLP; nsc broadcast via shuffle, multi-accumulator ----
    float h1a = 0.0f, h1b = 0.0f, h1c = 0.0f;
    #pragma unroll
    for (int i = 0; i < 27; ++i) {
        const int i0 = i, i1 = i + 27, i2 = i + 54;
        h1a = fmaf(__shfl_sync(0xFFFFFFFFu, v[i0 >> 5], i0 & 31), __ldg(W1 + i0 * HID + lane), h1a);
        h1b = fmaf(__shfl_sync(0xFFFFFFFFu, v[i1 >> 5], i1 & 31), __ldg(W1 + i1 * HID + lane), h1b);
        h1c = fmaf(__shfl_sync(0xFFFFFFFFu, v[i2 >> 5], i2 & 31), __ldg(W1 + i2 * HID + lane), h1c);
    }
    const float h1 = fmaxf(h1a + h1b + h1c, 0.0f);

    float h2a = 0.0f, h2b = 0.0f;
    #pragma unroll
    for (int m = 0; m < 16; ++m) {
        h2a = fmaf(__shfl_sync(0xFFFFFFFFu, h1, m),      __ldg(W2 + m * HID + lane),        h2a);
        h2b = fmaf(__shfl_sync(0xFFFFFFFFu, h1, m + 16), __ldg(W2 + (m + 16) * HID + lane), h2b);
    }
    const float h2 = fmaxf(h2a + h2b, 0.0f);

    float contrib = h2 * __ldg(W3 + lane);
    #pragma unroll
    for (int o = 16; o > 0; o >>= 1)
        contrib += __shfl_down_sync(0xFFFFFFFFu, contrib, o);

    if (lane == 0) {
        const float nr = contrib + __ldg(b3);
        __stcs(out + b,          imm + nr);
        __stcs(out + NB + b,     imm);
        __stcs(out + 2 * NB + b, nr);
    }
}

extern "C" void kernel_launch(void* const* d_in, const int* in_sizes, int n_in,
                              void* d_out, int out_size)
{
    const float* obs = (const float*)d_in[0];
    const float* ac  = (const float*)d_in[1];
    const float* W1  = (const float*)d_in[2];
    const float* W2  = (const float*)d_in[3];
    const float* W3  = (const float*)d_in[4];
    const float* b3  = (const float*)d_in[5];
    float* out = (float*)d_out;

    gdvpn_kernel<<<NB / BPB, NTHREADS>>>(obs, ac, W1, W2, W3, b3, out);
}